// round 12
// baseline (speedup 1.0000x reference)
#include <cuda_runtime.h>

typedef unsigned long long u64;

#define Bn 16
#define Hn 1024
#define Tn 4096
#define CDn 8
#define CSn 1024

#define THREADS 256
#define TT 128
#define TILES_PER_B (Tn / TT)        // 32
#define NBLK (Bn * TILES_PER_B)      // 512

#define OUT_N ((size_t)Bn * Hn * Tn)
#define LOSS_OFF (OUT_N)
#define IDX_OFF (OUT_N + 2)
#define PROJ_OFF (OUT_N + 2 + (size_t)Bn * Tn)

__device__ float g_losspart[NBLK];
__device__ unsigned int g_count;

__device__ __forceinline__ u64 pack2(float x, float y) {
    u64 r; asm("mov.b64 %0, {%1,%2};" : "=l"(r) : "f"(x), "f"(y)); return r;
}
__device__ __forceinline__ void unpack2(u64 v, float& x, float& y) {
    asm("mov.b64 {%0,%1}, %2;" : "=f"(x), "=f"(y) : "l"(v));
}
__device__ __forceinline__ u64 ffma2(u64 a, u64 b, u64 c) {
    u64 d; asm("fma.rn.f32x2 %0, %1, %2, %3;" : "=l"(d) : "l"(a), "l"(b), "l"(c)); return d;
}
__device__ __forceinline__ void pfL2(const void* p) {
    asm volatile("prefetch.global.L2 [%0];" :: "l"(p));
}

// smem float layout:
//   [0,9216)      buf : ws(8192) | cbs(8192)+cb2s(1024) | wos(8192)+bos(1024)
//   [9216,10240)  xfer : proj handoff, 128 t x 8 d
//   [10240,10624) sbestg : float2[3][64]
//   [10624,11008) sidxg  : int2[3][64]
//   [11008,11136) sidxf  : int2[64]  (combined winners)
//   [11136,11138) wsum
#define SMEM_FLOATS 11144
extern __shared__ float smem[];

__global__ __launch_bounds__(THREADS, 4) void main_kernel(
    const float* __restrict__ hid,   // [B,H,T]
    const float* __restrict__ w_in,  // [CD,H]
    const float* __restrict__ b_in,  // [CD]
    const float* __restrict__ w_out, // [H,CD]
    const float* __restrict__ b_out, // [H]
    const float* __restrict__ cb,    // [CS,CD]
    float* __restrict__ dout)
{
    float*  buf    = smem;
    float*  xfer   = smem + 9216;
    float2* sbestg = reinterpret_cast<float2*>(smem + 10240);
    int2*   sidxg  = reinterpret_cast<int2*>(smem + 10624);
    int2*   sidxf  = reinterpret_cast<int2*>(smem + 11008);
    float*  wsum   = smem + 11136;
    __shared__ unsigned int s_is_last;

    const int tid  = threadIdx.x;
    const int lane = tid & 31;
    const int blk  = blockIdx.x;
    const int b    = blk >> 5;
    const int t0   = (blk & 31) << 7;

    // ---- fill ws[h][d] from w_in[d][h] (vector loads, scalar scatter) -----
    {
        const float4* wiv = reinterpret_cast<const float4*>(w_in);
#pragma unroll
        for (int k = 0; k < 8; k++) {
            int i4 = tid + THREADS * k;          // float4 index in [0,2048)
            float4 w = __ldg(wiv + i4);
            int d = i4 >> 8;                     // (i4*4) >> 10
            int h = (i4 << 2) & 1023;
            buf[(h    ) * CDn + d] = w.x;
            buf[(h + 1) * CDn + d] = w.y;
            buf[(h + 2) * CDn + d] = w.z;
            buf[(h + 3) * CDn + d] = w.w;
        }
    }
    __syncthreads();

    // ================= Phase 1: proj. 2 threads per t (4 d each) ===========
    {
        const int half = tid >> 7;        // 0: d0-3, 1: d4-7
        const int tcol = tid & 127;
        const bool dopf = (half == 0);    // warp-uniform
        u64 acc0 = 0ULL, acc1 = 0ULL;
        const float* xp = hid + (size_t)b * Hn * Tn + (t0 + tcol);
        const float* wbase = buf + 4 * half;

#define PF 32
#pragma unroll 8
        for (int h = 0; h < Hn - PF; h++) {
            // one pf issue per 8 h: lanes 0-7 cover rows h+PF .. h+PF+7
            if (((h & 7) == 0) && dopf && (lane < 8))
                pfL2(xp + (size_t)(h + PF + lane) * Tn);
            float x = __ldg(xp + (size_t)h * Tn);
            u64 xd = pack2(x, x);
            ulonglong2 w = *reinterpret_cast<const ulonglong2*>(wbase + h * CDn);
            acc0 = ffma2(w.x, xd, acc0);
            acc1 = ffma2(w.y, xd, acc1);
        }
#pragma unroll 8
        for (int h = Hn - PF; h < Hn; h++) {
            float x = __ldg(xp + (size_t)h * Tn);
            u64 xd = pack2(x, x);
            ulonglong2 w = *reinterpret_cast<const ulonglong2*>(wbase + h * CDn);
            acc0 = ffma2(w.x, xd, acc0);
            acc1 = ffma2(w.y, xd, acc1);
        }
#undef PF
        float p[4];
        unpack2(acc0, p[0], p[1]);
        unpack2(acc1, p[2], p[3]);
#pragma unroll
        for (int d = 0; d < 4; d++) {
            float v = __fadd_rn(p[d], __ldg(b_in + 4 * half + d));
            xfer[tcol * CDn + 4 * half + d] = v;
            __stcs(dout + PROJ_OFF + ((size_t)b * CDn + 4 * half + d) * Tn + (t0 + tcol), v);
        }
    }
    __syncthreads();

    // ---- normalized codebook into cbs/cb2s (identical math) ----------------
    float* cbs  = buf;
    float* cb2s = buf + CSn * CDn;
#pragma unroll
    for (int k = 0; k < 4; k++) {
        int j = tid + THREADS * k;
        const float4* cr = reinterpret_cast<const float4*>(cb + j * CDn);
        float4 ca = __ldg(cr), cbv4 = __ldg(cr + 1);
        float v[CDn] = {ca.x, ca.y, ca.z, ca.w, cbv4.x, cbv4.y, cbv4.z, cbv4.w};
        float s = 0.f;
#pragma unroll
        for (int d = 0; d < CDn; d++) s = __fadd_rn(s, __fmul_rn(v[d], v[d]));
        float m = fmaxf(__fsqrt_rn(s), 1e-12f);
        float cd[CDn];
        float s2 = 0.f;
#pragma unroll
        for (int d = 0; d < CDn; d++) {
            cd[d] = __fdiv_rn(v[d], m);
            s2 = __fadd_rn(s2, __fmul_rn(cd[d], cd[d]));
        }
        float4* dst = reinterpret_cast<float4*>(cbs + j * CDn);
        dst[0] = make_float4(cd[0], cd[1], cd[2], cd[3]);
        dst[1] = make_float4(cd[4], cd[5], cd[6], cd[7]);
        cb2s[j] = s2;
    }
    __syncthreads();

    // ================= Phase 2: argmax. 2 t/thread, j split 4-way ===========
    const int pr  = tid & 63;
    const int grp = tid >> 6;

    float l20, l21;
    u64 ed0[4], ed1[4];
    float p0[CDn], p1[CDn];
    {
        const float4* x0 = reinterpret_cast<const float4*>(xfer + (2 * pr) * CDn);
        const float4* x1 = reinterpret_cast<const float4*>(xfer + (2 * pr + 1) * CDn);
        float4 a0 = x0[0], a1 = x0[1], c0 = x1[0], c1 = x1[1];
        p0[0]=a0.x; p0[1]=a0.y; p0[2]=a0.z; p0[3]=a0.w;
        p0[4]=a1.x; p0[5]=a1.y; p0[6]=a1.z; p0[7]=a1.w;
        p1[0]=c0.x; p1[1]=c0.y; p1[2]=c0.z; p1[3]=c0.w;
        p1[4]=c1.x; p1[5]=c1.y; p1[6]=c1.z; p1[7]=c1.w;

        float l2r0 = 0.f, l2r1 = 0.f;
#pragma unroll
        for (int d = 0; d < CDn; d++) {
            l2r0 = __fadd_rn(l2r0, __fmul_rn(p0[d], p0[d]));
            l2r1 = __fadd_rn(l2r1, __fmul_rn(p1[d], p1[d]));
        }
        float den0 = fmaxf(__fsqrt_rn(l2r0), 1e-12f);
        float den1 = fmaxf(__fsqrt_rn(l2r1), 1e-12f);
        float e0[CDn], e1[CDn];
        l20 = 0.f; l21 = 0.f;
#pragma unroll
        for (int d = 0; d < CDn; d++) {
            e0[d] = __fdiv_rn(p0[d], den0);
            e1[d] = __fdiv_rn(p1[d], den1);
            l20 = __fadd_rn(l20, __fmul_rn(e0[d], e0[d]));
            l21 = __fadd_rn(l21, __fmul_rn(e1[d], e1[d]));
        }
#pragma unroll
        for (int q = 0; q < 4; q++) {
            ed0[q] = pack2(e0[2 * q], e0[2 * q + 1]);
            ed1[q] = pack2(e1[2 * q], e1[2 * q + 1]);
        }
    }

    const int jstart = grp << 8;
    float best0 = -3.402823466e38f, best1 = -3.402823466e38f;
    int i0 = jstart, i1 = jstart;
#pragma unroll 2
    for (int j = jstart; j < jstart + 256; j += 2) {
        const ulonglong2* crA = reinterpret_cast<const ulonglong2*>(cbs + j * CDn);
        ulonglong2 caA = crA[0], cbA = crA[1];
        ulonglong2 caB = crA[2], cbB = crA[3];
        float2 cb2p = *reinterpret_cast<const float2*>(cb2s + j);

        // ---- j ----
        {
            u64 a = ffma2(ed0[0], caA.x, 0ULL);
            a = ffma2(ed0[1], caA.y, a); a = ffma2(ed0[2], cbA.x, a); a = ffma2(ed0[3], cbA.y, a);
            float alo, ahi; unpack2(a, alo, ahi);
            float dot0 = __fadd_rn(alo, ahi);
            float s0 = __fsub_rn(cb2p.x, __fmaf_rn(-2.f, dot0, l20));
            if (s0 > best0) { best0 = s0; i0 = j; }

            u64 bq = ffma2(ed1[0], caA.x, 0ULL);
            bq = ffma2(ed1[1], caA.y, bq); bq = ffma2(ed1[2], cbA.x, bq); bq = ffma2(ed1[3], cbA.y, bq);
            float blo, bhi; unpack2(bq, blo, bhi);
            float dot1 = __fadd_rn(blo, bhi);
            float s1 = __fsub_rn(cb2p.x, __fmaf_rn(-2.f, dot1, l21));
            if (s1 > best1) { best1 = s1; i1 = j; }
        }
        // ---- j + 1 ----
        {
            u64 a = ffma2(ed0[0], caB.x, 0ULL);
            a = ffma2(ed0[1], caB.y, a); a = ffma2(ed0[2], cbB.x, a); a = ffma2(ed0[3], cbB.y, a);
            float alo, ahi; unpack2(a, alo, ahi);
            float dot0 = __fadd_rn(alo, ahi);
            float s0 = __fsub_rn(cb2p.y, __fmaf_rn(-2.f, dot0, l20));
            if (s0 > best0) { best0 = s0; i0 = j + 1; }

            u64 bq = ffma2(ed1[0], caB.x, 0ULL);
            bq = ffma2(ed1[1], caB.y, bq); bq = ffma2(ed1[2], cbB.x, bq); bq = ffma2(ed1[3], cbB.y, bq);
            float blo, bhi; unpack2(bq, blo, bhi);
            float dot1 = __fadd_rn(blo, bhi);
            float s1 = __fsub_rn(cb2p.y, __fmaf_rn(-2.f, dot1, l21));
            if (s1 > best1) { best1 = s1; i1 = j + 1; }
        }
    }
    if (grp) {
        sbestg[(grp - 1) * 64 + pr] = make_float2(best0, best1);
        sidxg[(grp - 1) * 64 + pr]  = make_int2(i0, i1);
    }
    __syncthreads();

    // ---- fill wos/bos (all threads, overwrites cbs) + g0 combine/epilogue --
    float* wos = buf;
    float* bos = buf + Hn * CDn;
    {
        const float4* wov = reinterpret_cast<const float4*>(w_out);
        float4* wod = reinterpret_cast<float4*>(wos);
#pragma unroll
        for (int k = 0; k < 8; k++) {
            int idx = tid + THREADS * k;
            wod[idx] = __ldg(wov + idx);
        }
#pragma unroll
        for (int k = 0; k < 4; k++) {
            int idx = tid + THREADS * k;
            bos[idx] = b_out[idx];
        }
    }

    if (grp == 0) {
        // combine in ascending-j group order: strict > keeps first max (exact)
#pragma unroll
        for (int g = 0; g < 3; g++) {
            float2 bb = sbestg[g * 64 + pr];
            int2   ii = sidxg[g * 64 + pr];
            if (bb.x > best0) { best0 = bb.x; i0 = ii.x; }
            if (bb.y > best1) { best1 = bb.y; i1 = ii.y; }
        }
        sidxf[pr] = make_int2(i0, i1);
        __stcs(reinterpret_cast<float2*>(dout + IDX_OFF + (size_t)b * Tn + t0 + 2 * pr),
               make_float2((float)i0, (float)i1));

        // loss partial: p kept in regs, q from codebook
        const float4* cbv = reinterpret_cast<const float4*>(cb);
        float4 qa0 = __ldg(cbv + i0 * 2), qb0 = __ldg(cbv + i0 * 2 + 1);
        float4 qa1 = __ldg(cbv + i1 * 2), qb1 = __ldg(cbv + i1 * 2 + 1);
        float q0[CDn] = {qa0.x, qa0.y, qa0.z, qa0.w, qb0.x, qb0.y, qb0.z, qb0.w};
        float q1[CDn] = {qa1.x, qa1.y, qa1.z, qa1.w, qb1.x, qb1.y, qb1.z, qb1.w};

        float ls = 0.f;
#pragma unroll
        for (int d = 0; d < CDn; d++) {
            float a = p0[d] - q0[d]; ls = __fmaf_rn(a, a, ls);
            float c = p1[d] - q1[d]; ls = __fmaf_rn(c, c, ls);
        }
#pragma unroll
        for (int o = 16; o; o >>= 1) ls += __shfl_xor_sync(0xFFFFFFFFu, ls, o);
        if ((tid & 31) == 0) wsum[tid >> 5] = ls;
    }
    __syncthreads();
    if (tid == 0) g_losspart[blk] = wsum[0] + wsum[1];

    // ================= Phase 3: out. 2 t/thread, h split 4-way ==============
    {
        int2 ji = sidxf[pr];
        const float4* cbv = reinterpret_cast<const float4*>(cb);
        float4 qa0 = __ldg(cbv + ji.x * 2), qb0 = __ldg(cbv + ji.x * 2 + 1);
        float4 qa1 = __ldg(cbv + ji.y * 2), qb1 = __ldg(cbv + ji.y * 2 + 1);

        u64 qp0[4], qp1[4];
        qp0[0] = pack2(qa0.x, qa0.y); qp0[1] = pack2(qa0.z, qa0.w);
        qp0[2] = pack2(qb0.x, qb0.y); qp0[3] = pack2(qb0.z, qb0.w);
        qp1[0] = pack2(qa1.x, qa1.y); qp1[1] = pack2(qa1.z, qa1.w);
        qp1[2] = pack2(qb1.x, qb1.y); qp1[3] = pack2(qb1.z, qb1.w);

        float* outbase = dout + (size_t)b * Hn * Tn + (t0 + 2 * pr);
        const int hbase = grp << 8;
#pragma unroll 4
        for (int hh = 0; hh < 256; hh++) {
            int h = hbase + hh;
            const ulonglong2* wr2 = reinterpret_cast<const ulonglong2*>(wos + h * CDn);
            ulonglong2 wa = wr2[0], wb = wr2[1];
            u64 bd = pack2(bos[h], 0.0f);   // bias enters each chain exactly once

            u64 a = ffma2(qp0[0], wa.x, bd);
            a = ffma2(qp0[1], wa.y, a); a = ffma2(qp0[2], wb.x, a); a = ffma2(qp0[3], wb.y, a);
            float alo, ahi; unpack2(a, alo, ahi);
            float o0 = __fadd_rn(alo, ahi);

            u64 c = ffma2(qp1[0], wa.x, bd);
            c = ffma2(qp1[1], wa.y, c); c = ffma2(qp1[2], wb.x, c); c = ffma2(qp1[3], wb.y, c);
            float clo, chi; unpack2(c, clo, chi);
            float o1 = __fadd_rn(clo, chi);

            __stcs(reinterpret_cast<float2*>(outbase + (size_t)h * Tn), make_float2(o0, o1));
        }
    }

    // ---- last block finalizes loss mean (whole block participates) ---------
    __syncthreads();
    if (tid == 0) {
        __threadfence();
        unsigned int c = atomicAdd(&g_count, 1u);
        s_is_last = (c == NBLK - 1) ? 1u : 0u;
        if (s_is_last) g_count = 0;
    }
    __syncthreads();
    if (s_is_last) {
        float v = __ldcg(g_losspart + tid) + __ldcg(g_losspart + tid + THREADS);
#pragma unroll
        for (int o = 16; o; o >>= 1) v += __shfl_xor_sync(0xFFFFFFFFu, v, o);
        __syncthreads();
        if ((tid & 31) == 0) sbestg[tid >> 5].x = v;
        __syncthreads();
        if (tid == 0) {
            float tot = 0.f;
#pragma unroll
            for (int w = 0; w < THREADS / 32; w++) tot += sbestg[w].x;
            float mean = tot * (1.0f / (float)(Bn * CDn * Tn));
            dout[LOSS_OFF]     = mean;
            dout[LOSS_OFF + 1] = mean;
        }
    }
}

// ---------------------------------------------------------------------------
extern "C" void kernel_launch(void* const* d_in, const int* in_sizes, int n_in,
                              void* d_out, int out_size) {
    const float* hid   = (const float*)d_in[0];
    const float* w_in  = (const float*)d_in[1];
    const float* b_in  = (const float*)d_in[2];
    const float* w_out = (const float*)d_in[3];
    const float* b_out = (const float*)d_in[4];
    const float* cb    = (const float*)d_in[5];
    float* dout = (float*)d_out;

    const int smem_bytes = SMEM_FLOATS * 4;  // 44576 B
    cudaFuncSetAttribute(main_kernel, cudaFuncAttributeMaxDynamicSharedMemorySize, smem_bytes);

    main_kernel<<<NBLK, THREADS, smem_bytes>>>(hid, w_in, b_in, w_out, b_out, cb, dout);
}

// round 13
// speedup vs baseline: 1.1086x; 1.1086x over previous
#include <cuda_runtime.h>

typedef unsigned long long u64;

#define Bn 16
#define Hn 1024
#define Tn 4096
#define CDn 8
#define CSn 1024

#define THREADS 256
#define TT 256
#define TILES_PER_B (Tn / TT)        // 16
#define NBLK (Bn * TILES_PER_B)      // 256

#define OUT_N ((size_t)Bn * Hn * Tn)
#define LOSS_OFF (OUT_N)
#define IDX_OFF (OUT_N + 2)
#define PROJ_OFF (OUT_N + 2 + (size_t)Bn * Tn)

__device__ float g_losspart[NBLK];
__device__ unsigned int g_count;

__device__ __forceinline__ u64 pack2(float x, float y) {
    u64 r; asm("mov.b64 %0, {%1,%2};" : "=l"(r) : "f"(x), "f"(y)); return r;
}
__device__ __forceinline__ void unpack2(u64 v, float& x, float& y) {
    asm("mov.b64 {%0,%1}, %2;" : "=f"(x), "=f"(y) : "l"(v));
}
__device__ __forceinline__ u64 ffma2(u64 a, u64 b, u64 c) {
    u64 d; asm("fma.rn.f32x2 %0, %1, %2, %3;" : "=l"(d) : "l"(a), "l"(b), "l"(c)); return d;
}
__device__ __forceinline__ void pfL2(const void* p) {
    asm volatile("prefetch.global.L2 [%0];" :: "l"(p));
}

// smem float layout:
//   [0,9216)      buf : ws(8192) | cbs(8192)+cb2s(1024) | wos(8192)+bos(1024)
//   [9216,11264)  xfer : proj handoff, 256 t x 8 d
//   [11264,11520) sbestg : float2[128]   (group-1 partials)
//   [11520,11776) sidxg  : int2[128]
//   [11776,12032) sidxf  : int2[128]     (combined winners)
//   [12032,12036) wsum
#define SMEM_FLOATS 12040
extern __shared__ float smem[];

__global__ __launch_bounds__(THREADS, 4) void main_kernel(
    const float* __restrict__ hid,   // [B,H,T]
    const float* __restrict__ w_in,  // [CD,H]
    const float* __restrict__ b_in,  // [CD]
    const float* __restrict__ w_out, // [H,CD]
    const float* __restrict__ b_out, // [H]
    const float* __restrict__ cb,    // [CS,CD]
    float* __restrict__ dout)
{
    float*  buf    = smem;
    float*  xfer   = smem + 9216;
    float2* sbestg = reinterpret_cast<float2*>(smem + 11264);
    int2*   sidxg  = reinterpret_cast<int2*>(smem + 11520);
    int2*   sidxf  = reinterpret_cast<int2*>(smem + 11776);
    float*  wsum   = smem + 12032;
    __shared__ unsigned int s_is_last;

    const int tid = threadIdx.x;
    const int blk = blockIdx.x;
    const int b   = blk >> 4;
    const int t0  = (blk & 15) << 8;

    // ---- fill ws[h][d] from w_in[d][h] (R11 verbatim) ---------------------
#pragma unroll
    for (int k = 0; k < 32; k++) {
        int idx = tid + THREADS * k;
        int d = idx >> 10, h = idx & 1023;
        buf[h * CDn + d] = w_in[idx];
    }
    __syncthreads();

    // ===== Phase 1: proj. thread = t-pair (2t) x d-half (4d) ===============
    {
        const int u  = tid & 127;         // t-pair index: t = 2u, 2u+1
        const int dh = tid >> 7;          // 0: d0-3, 1: d4-7
        const bool dopf = (dh == 0);      // warp-uniform
        const int dbase = 4 * dh;
        u64 aA0 = 0ULL, aA1 = 0ULL, aB0 = 0ULL, aB1 = 0ULL;
        const float* xp = hid + (size_t)b * Hn * Tn + (t0 + 2 * u);
        const float* wbase = buf + dbase;

#define PF 32
#pragma unroll 8
        for (int h = 0; h < Hn - PF; h++) {
            if (dopf) pfL2(xp + (size_t)(h + PF) * Tn);
            float2 x = __ldg(reinterpret_cast<const float2*>(xp + (size_t)h * Tn));
            u64 x0 = pack2(x.x, x.x);
            u64 x1 = pack2(x.y, x.y);
            ulonglong2 w = *reinterpret_cast<const ulonglong2*>(wbase + h * CDn);
            aA0 = ffma2(w.x, x0, aA0);
            aA1 = ffma2(w.y, x0, aA1);
            aB0 = ffma2(w.x, x1, aB0);
            aB1 = ffma2(w.y, x1, aB1);
        }
#pragma unroll 8
        for (int h = Hn - PF; h < Hn; h++) {
            float2 x = __ldg(reinterpret_cast<const float2*>(xp + (size_t)h * Tn));
            u64 x0 = pack2(x.x, x.x);
            u64 x1 = pack2(x.y, x.y);
            ulonglong2 w = *reinterpret_cast<const ulonglong2*>(wbase + h * CDn);
            aA0 = ffma2(w.x, x0, aA0);
            aA1 = ffma2(w.y, x0, aA1);
            aB0 = ffma2(w.x, x1, aB0);
            aB1 = ffma2(w.y, x1, aB1);
        }
#undef PF
        float pA[4], pB[4];
        unpack2(aA0, pA[0], pA[1]);
        unpack2(aA1, pA[2], pA[3]);
        unpack2(aB0, pB[0], pB[1]);
        unpack2(aB1, pB[2], pB[3]);
#pragma unroll
        for (int d = 0; d < 4; d++) {
            float bb = __ldg(b_in + dbase + d);
            float vA = __fadd_rn(pA[d], bb);
            float vB = __fadd_rn(pB[d], bb);
            xfer[(2 * u) * CDn + dbase + d]     = vA;
            xfer[(2 * u + 1) * CDn + dbase + d] = vB;
            __stcs(reinterpret_cast<float2*>(
                       dout + PROJ_OFF + ((size_t)b * CDn + dbase + d) * Tn + (t0 + 2 * u)),
                   make_float2(vA, vB));
        }
    }
    __syncthreads();

    // ---- normalized codebook into cbs/cb2s (identical math) ----------------
    float* cbs  = buf;
    float* cb2s = buf + CSn * CDn;
#pragma unroll
    for (int k = 0; k < 4; k++) {
        int j = tid + THREADS * k;
        const float4* cr = reinterpret_cast<const float4*>(cb + j * CDn);
        float4 ca = __ldg(cr), cbv4 = __ldg(cr + 1);
        float v[CDn] = {ca.x, ca.y, ca.z, ca.w, cbv4.x, cbv4.y, cbv4.z, cbv4.w};
        float s = 0.f;
#pragma unroll
        for (int d = 0; d < CDn; d++) s = __fadd_rn(s, __fmul_rn(v[d], v[d]));
        float m = fmaxf(__fsqrt_rn(s), 1e-12f);
        float cd[CDn];
        float s2 = 0.f;
#pragma unroll
        for (int d = 0; d < CDn; d++) {
            cd[d] = __fdiv_rn(v[d], m);
            s2 = __fadd_rn(s2, __fmul_rn(cd[d], cd[d]));
        }
        float4* dst = reinterpret_cast<float4*>(cbs + j * CDn);
        dst[0] = make_float4(cd[0], cd[1], cd[2], cd[3]);
        dst[1] = make_float4(cd[4], cd[5], cd[6], cd[7]);
        cb2s[j] = s2;
    }
    __syncthreads();

    // ===== Phase 2: argmax. 2 t/thread, j split 2-way ======================
    const int pr  = tid & 127;
    const int grp = tid >> 7;

    float l20, l21;
    u64 ed0[4], ed1[4];
    float p0[CDn], p1[CDn];
    {
        const float4* x0 = reinterpret_cast<const float4*>(xfer + (2 * pr) * CDn);
        const float4* x1 = reinterpret_cast<const float4*>(xfer + (2 * pr + 1) * CDn);
        float4 a0 = x0[0], a1 = x0[1], c0 = x1[0], c1 = x1[1];
        p0[0]=a0.x; p0[1]=a0.y; p0[2]=a0.z; p0[3]=a0.w;
        p0[4]=a1.x; p0[5]=a1.y; p0[6]=a1.z; p0[7]=a1.w;
        p1[0]=c0.x; p1[1]=c0.y; p1[2]=c0.z; p1[3]=c0.w;
        p1[4]=c1.x; p1[5]=c1.y; p1[6]=c1.z; p1[7]=c1.w;

        float l2r0 = 0.f, l2r1 = 0.f;
#pragma unroll
        for (int d = 0; d < CDn; d++) {
            l2r0 = __fadd_rn(l2r0, __fmul_rn(p0[d], p0[d]));
            l2r1 = __fadd_rn(l2r1, __fmul_rn(p1[d], p1[d]));
        }
        float den0 = fmaxf(__fsqrt_rn(l2r0), 1e-12f);
        float den1 = fmaxf(__fsqrt_rn(l2r1), 1e-12f);
        float e0[CDn], e1[CDn];
        l20 = 0.f; l21 = 0.f;
#pragma unroll
        for (int d = 0; d < CDn; d++) {
            e0[d] = __fdiv_rn(p0[d], den0);
            e1[d] = __fdiv_rn(p1[d], den1);
            l20 = __fadd_rn(l20, __fmul_rn(e0[d], e0[d]));
            l21 = __fadd_rn(l21, __fmul_rn(e1[d], e1[d]));
        }
#pragma unroll
        for (int q = 0; q < 4; q++) {
            ed0[q] = pack2(e0[2 * q], e0[2 * q + 1]);
            ed1[q] = pack2(e1[2 * q], e1[2 * q + 1]);
        }
    }

    const int jstart = grp << 9;
    float best0 = -3.402823466e38f, best1 = -3.402823466e38f;
    int i0 = jstart, i1 = jstart;
#pragma unroll 2
    for (int j = jstart; j < jstart + 512; j += 2) {
        const ulonglong2* crA = reinterpret_cast<const ulonglong2*>(cbs + j * CDn);
        ulonglong2 caA = crA[0], cbA = crA[1];
        ulonglong2 caB = crA[2], cbB = crA[3];
        float2 cb2p = *reinterpret_cast<const float2*>(cb2s + j);

        // ---- j ----
        {
            u64 a = ffma2(ed0[0], caA.x, 0ULL);
            a = ffma2(ed0[1], caA.y, a); a = ffma2(ed0[2], cbA.x, a); a = ffma2(ed0[3], cbA.y, a);
            float alo, ahi; unpack2(a, alo, ahi);
            float dot0 = __fadd_rn(alo, ahi);
            float s0 = __fsub_rn(cb2p.x, __fmaf_rn(-2.f, dot0, l20));
            if (s0 > best0) { best0 = s0; i0 = j; }

            u64 bq = ffma2(ed1[0], caA.x, 0ULL);
            bq = ffma2(ed1[1], caA.y, bq); bq = ffma2(ed1[2], cbA.x, bq); bq = ffma2(ed1[3], cbA.y, bq);
            float blo, bhi; unpack2(bq, blo, bhi);
            float dot1 = __fadd_rn(blo, bhi);
            float s1 = __fsub_rn(cb2p.x, __fmaf_rn(-2.f, dot1, l21));
            if (s1 > best1) { best1 = s1; i1 = j; }
        }
        // ---- j + 1 ----
        {
            u64 a = ffma2(ed0[0], caB.x, 0ULL);
            a = ffma2(ed0[1], caB.y, a); a = ffma2(ed0[2], cbB.x, a); a = ffma2(ed0[3], cbB.y, a);
            float alo, ahi; unpack2(a, alo, ahi);
            float dot0 = __fadd_rn(alo, ahi);
            float s0 = __fsub_rn(cb2p.y, __fmaf_rn(-2.f, dot0, l20));
            if (s0 > best0) { best0 = s0; i0 = j + 1; }

            u64 bq = ffma2(ed1[0], caB.x, 0ULL);
            bq = ffma2(ed1[1], caB.y, bq); bq = ffma2(ed1[2], cbB.x, bq); bq = ffma2(ed1[3], cbB.y, bq);
            float blo, bhi; unpack2(bq, blo, bhi);
            float dot1 = __fadd_rn(blo, bhi);
            float s1 = __fsub_rn(cb2p.y, __fmaf_rn(-2.f, dot1, l21));
            if (s1 > best1) { best1 = s1; i1 = j + 1; }
        }
    }
    if (grp) {
        sbestg[pr] = make_float2(best0, best1);
        sidxg[pr]  = make_int2(i0, i1);
    }
    __syncthreads();

    // ---- fill wos/bos (all threads, overwrites cbs) + g0 combine/epilogue --
    float* wos = buf;
    float* bos = buf + Hn * CDn;
    {
        const float4* wov = reinterpret_cast<const float4*>(w_out);
        float4* wod = reinterpret_cast<float4*>(wos);
#pragma unroll
        for (int k = 0; k < 8; k++) {
            int idx = tid + THREADS * k;
            wod[idx] = __ldg(wov + idx);
        }
#pragma unroll
        for (int k = 0; k < 4; k++) {
            int idx = tid + THREADS * k;
            bos[idx] = b_out[idx];
        }
    }

    if (grp == 0) {
        // combine ascending-j (grp0 local, then grp1): strict > keeps first max
        {
            float2 bb = sbestg[pr];
            int2   ii = sidxg[pr];
            if (bb.x > best0) { best0 = bb.x; i0 = ii.x; }
            if (bb.y > best1) { best1 = bb.y; i1 = ii.y; }
        }
        sidxf[pr] = make_int2(i0, i1);
        __stcs(reinterpret_cast<float2*>(dout + IDX_OFF + (size_t)b * Tn + t0 + 2 * pr),
               make_float2((float)i0, (float)i1));

        // loss partial: p kept in regs, q from codebook
        const float4* cbv = reinterpret_cast<const float4*>(cb);
        float4 qa0 = __ldg(cbv + i0 * 2), qb0 = __ldg(cbv + i0 * 2 + 1);
        float4 qa1 = __ldg(cbv + i1 * 2), qb1 = __ldg(cbv + i1 * 2 + 1);
        float q0[CDn] = {qa0.x, qa0.y, qa0.z, qa0.w, qb0.x, qb0.y, qb0.z, qb0.w};
        float q1[CDn] = {qa1.x, qa1.y, qa1.z, qa1.w, qb1.x, qb1.y, qb1.z, qb1.w};

        float ls = 0.f;
#pragma unroll
        for (int d = 0; d < CDn; d++) {
            float a = p0[d] - q0[d]; ls = __fmaf_rn(a, a, ls);
            float c = p1[d] - q1[d]; ls = __fmaf_rn(c, c, ls);
        }
#pragma unroll
        for (int o = 16; o; o >>= 1) ls += __shfl_xor_sync(0xFFFFFFFFu, ls, o);
        if ((tid & 31) == 0) wsum[tid >> 5] = ls;
    }
    __syncthreads();
    if (tid == 0) g_losspart[blk] = (wsum[0] + wsum[1]) + (wsum[2] + wsum[3]);

    // ===== Phase 3: out. 2 t/thread, h split 2-way =========================
    {
        int2 ji = sidxf[pr];
        const float4* cbv = reinterpret_cast<const float4*>(cb);
        float4 qa0 = __ldg(cbv + ji.x * 2), qb0 = __ldg(cbv + ji.x * 2 + 1);
        float4 qa1 = __ldg(cbv + ji.y * 2), qb1 = __ldg(cbv + ji.y * 2 + 1);

        u64 qp0[4], qp1[4];
        qp0[0] = pack2(qa0.x, qa0.y); qp0[1] = pack2(qa0.z, qa0.w);
        qp0[2] = pack2(qb0.x, qb0.y); qp0[3] = pack2(qb0.z, qb0.w);
        qp1[0] = pack2(qa1.x, qa1.y); qp1[1] = pack2(qa1.z, qa1.w);
        qp1[2] = pack2(qb1.x, qb1.y); qp1[3] = pack2(qb1.z, qb1.w);

        float* outbase = dout + (size_t)b * Hn * Tn + (t0 + 2 * pr);
        const int hbase = grp << 9;
#pragma unroll 4
        for (int hh = 0; hh < 512; hh++) {
            int h = hbase + hh;
            const ulonglong2* wr2 = reinterpret_cast<const ulonglong2*>(wos + h * CDn);
            ulonglong2 wa = wr2[0], wb = wr2[1];
            u64 bd = pack2(bos[h], 0.0f);   // bias enters each chain exactly once

            u64 a = ffma2(qp0[0], wa.x, bd);
            a = ffma2(qp0[1], wa.y, a); a = ffma2(qp0[2], wb.x, a); a = ffma2(qp0[3], wb.y, a);
            float alo, ahi; unpack2(a, alo, ahi);
            float o0 = __fadd_rn(alo, ahi);

            u64 c = ffma2(qp1[0], wa.x, bd);
            c = ffma2(qp1[1], wa.y, c); c = ffma2(qp1[2], wb.x, c); c = ffma2(qp1[3], wb.y, c);
            float clo, chi; unpack2(c, clo, chi);
            float o1 = __fadd_rn(clo, chi);

            __stcs(reinterpret_cast<float2*>(outbase + (size_t)h * Tn), make_float2(o0, o1));
        }
    }

    // ---- last block finalizes loss mean ------------------------------------
    __syncthreads();
    if (tid == 0) {
        __threadfence();
        unsigned int c = atomicAdd(&g_count, 1u);
        s_is_last = (c == NBLK - 1) ? 1u : 0u;
        if (s_is_last) g_count = 0;
    }
    __syncthreads();
    if (s_is_last) {
        float v = __ldcg(g_losspart + tid);
#pragma unroll
        for (int o = 16; o; o >>= 1) v += __shfl_xor_sync(0xFFFFFFFFu, v, o);
        __syncthreads();
        if ((tid & 31) == 0) sbestg[tid >> 5].x = v;
        __syncthreads();
        if (tid == 0) {
            float tot = 0.f;
#pragma unroll
            for (int w = 0; w < THREADS / 32; w++) tot += sbestg[w].x;
            float mean = tot * (1.0f / (float)(Bn * CDn * Tn));
            dout[LOSS_OFF]     = mean;
            dout[LOSS_OFF + 1] = mean;
        }
    }
}

// ---------------------------------------------------------------------------
extern "C" void kernel_launch(void* const* d_in, const int* in_sizes, int n_in,
                              void* d_out, int out_size) {
    const float* hid   = (const float*)d_in[0];
    const float* w_in  = (const float*)d_in[1];
    const float* b_in  = (const float*)d_in[2];
    const float* w_out = (const float*)d_in[3];
    const float* b_out = (const float*)d_in[4];
    const float* cb    = (const float*)d_in[5];
    float* dout = (float*)d_out;

    const int smem_bytes = SMEM_FLOATS * 4;  // 48160 B
    cudaFuncSetAttribute(main_kernel, cudaFuncAttributeMaxDynamicSharedMemorySize, smem_bytes);

    main_kernel<<<NBLK, THREADS, smem_bytes>>>(hid, w_in, b_in, w_out, b_out, cb, dout);
}